// round 3
// baseline (speedup 1.0000x reference)
#include <cuda_runtime.h>
#include <cstdint>

#define P_CHDROP 0.1f
#define NOISE_STD 0.02f
#define P_TIMEMASK 0.1f
#define T_DIM 2048
#define MLEN 32

// 4 float4 per thread, loads front-batched to maximize MLP / DRAM burst length.
// Block tile = 1024 float4; thread handles i, i+256, i+512, i+768 (fully coalesced).
__global__ void __launch_bounds__(256, 8)
eeg_augment_kernel(const float4* __restrict__ x,
                   const float4* __restrict__ chdrop_u,   // [B,32] float4 view of [B,1,N]
                   const float4* __restrict__ noise,
                   const float* __restrict__ tm_u,        // [B]
                   const int* __restrict__ t0,            // [B]
                   float4* __restrict__ out)
{
    const unsigned int base = blockIdx.x * 1024u + threadIdx.x;

    unsigned int idx[4];
    bool masked[4];
    float4 xv[4], nv[4], cu[4];

    // Phase 1: index math + front-batched loads (8 LDG.128 in flight)
    #pragma unroll
    for (int k = 0; k < 4; k++) {
        unsigned int i = base + (unsigned int)k * 256u;
        idx[k] = i;

        unsigned int n4 = i & 31u;
        unsigned int bt = i >> 5;
        unsigned int t  = bt & (T_DIM - 1);
        unsigned int b  = bt >> 11;

        float tu = __ldg(tm_u + b);
        int   ts = __ldg(t0 + b);
        masked[k] = (tu < P_TIMEMASK) & ((int)t >= ts) & ((int)t < ts + MLEN);

        xv[k] = __ldcs(x + i);
        nv[k] = __ldcs(noise + i);
        cu[k] = __ldg(chdrop_u + (b << 5) + n4);
    }

    // Phase 2: compute + streaming stores
    #pragma unroll
    for (int k = 0; k < 4; k++) {
        float4 o;
        if (masked[k]) {
            o.x = 0.0f; o.y = 0.0f; o.z = 0.0f; o.w = 0.0f;
        } else {
            o.x = (cu[k].x < P_CHDROP ? 0.0f : xv[k].x) + NOISE_STD * nv[k].x;
            o.y = (cu[k].y < P_CHDROP ? 0.0f : xv[k].y) + NOISE_STD * nv[k].y;
            o.z = (cu[k].z < P_CHDROP ? 0.0f : xv[k].z) + NOISE_STD * nv[k].z;
            o.w = (cu[k].w < P_CHDROP ? 0.0f : xv[k].w) + NOISE_STD * nv[k].w;
        }
        __stcs(out + idx[k], o);
    }
}

extern "C" void kernel_launch(void* const* d_in, const int* in_sizes, int n_in,
                              void* d_out, int out_size)
{
    // metadata order: x, chdrop_u, noise, tm_u, t0
    const float4* x      = (const float4*)d_in[0];
    const float4* cu     = (const float4*)d_in[1];
    const float4* noise  = (const float4*)d_in[2];
    const float*  tm_u   = (const float*)d_in[3];
    const int*    t0     = (const int*)d_in[4];
    float4*       out    = (float4*)d_out;

    // 256*2048*128 f32 = 16,777,216 float4; 1024 per block -> 16384 blocks
    const unsigned int blocks  = 16384u;
    const unsigned int threads = 256u;

    eeg_augment_kernel<<<blocks, threads>>>(x, cu, noise, tm_u, t0, out);
}

// round 4
// speedup vs baseline: 1.0297x; 1.0297x over previous
#include <cuda_runtime.h>
#include <cstdint>

#define P_CHDROP 0.1f
#define NOISE_STD 0.02f
#define P_TIMEMASK 0.1f
#define T_DIM 2048
#define MLEN 32

// Best-known shape (R2): 2 float4/thread, coalesced i and i+256 in a 512-vec tile.
// Change vs R2: x/noise use __ldlu (last-use, invalidate-on-read) instead of __ldcs,
// freeing L2 lines immediately -> longer DRAM write bursts, fewer rd/wr turnarounds.
__global__ void __launch_bounds__(256, 8)
eeg_augment_kernel(const float4* __restrict__ x,
                   const float4* __restrict__ chdrop_u,   // [B,32] float4 view of [B,1,N]
                   const float4* __restrict__ noise,
                   const float* __restrict__ tm_u,        // [B]
                   const int* __restrict__ t0,            // [B]
                   float4* __restrict__ out)
{
    unsigned int base = blockIdx.x * 512u + threadIdx.x;

    #pragma unroll
    for (int k = 0; k < 2; k++) {
        unsigned int i = base + (unsigned int)k * 256u;

        unsigned int n4 = i & 31u;           // float4 index within N (N/4 = 32)
        unsigned int bt = i >> 5;
        unsigned int t  = bt & (T_DIM - 1);  // T = 2048 = 2^11
        unsigned int b  = bt >> 11;

        float tu = __ldg(tm_u + b);
        int   ts = __ldg(t0 + b);
        bool masked = (tu < P_TIMEMASK) & ((int)t >= ts) & ((int)t < ts + MLEN);

        float4 o;
        if (masked) {
            o.x = 0.0f; o.y = 0.0f; o.z = 0.0f; o.w = 0.0f;
        } else {
            float4 xv = __ldlu(x + i);
            float4 nv = __ldlu(noise + i);
            float4 cu = __ldg(chdrop_u + (b << 5) + n4);   // tiny, reused -> keep cached

            o.x = (cu.x < P_CHDROP ? 0.0f : xv.x) + NOISE_STD * nv.x;
            o.y = (cu.y < P_CHDROP ? 0.0f : xv.y) + NOISE_STD * nv.y;
            o.z = (cu.z < P_CHDROP ? 0.0f : xv.z) + NOISE_STD * nv.z;
            o.w = (cu.w < P_CHDROP ? 0.0f : xv.w) + NOISE_STD * nv.w;
        }
        __stcs(out + i, o);
    }
}

extern "C" void kernel_launch(void* const* d_in, const int* in_sizes, int n_in,
                              void* d_out, int out_size)
{
    // metadata order: x, chdrop_u, noise, tm_u, t0
    const float4* x      = (const float4*)d_in[0];
    const float4* cu     = (const float4*)d_in[1];
    const float4* noise  = (const float4*)d_in[2];
    const float*  tm_u   = (const float*)d_in[3];
    const int*    t0     = (const int*)d_in[4];
    float4*       out    = (float4*)d_out;

    // 256*2048*128 f32 = 16,777,216 float4; 512 per block -> 32768 blocks
    const unsigned int blocks  = 32768u;
    const unsigned int threads = 256u;

    eeg_augment_kernel<<<blocks, threads>>>(x, cu, noise, tm_u, t0, out);
}

// round 5
// speedup vs baseline: 1.0337x; 1.0038x over previous
#include <cuda_runtime.h>
#include <cstdint>

#define P_CHDROP 0.1f
#define NOISE_STD 0.02f
#define P_TIMEMASK 0.1f
#define T_DIM 2048
#define MLEN 32

// Final variant: R2 shape (2 float4/thread, 512-vec tile, __ldcs/__stcs),
// plus block-uniform b: each block's 512 float4 live in one b (128 blocks/b),
// so tm_u/t0 are single uniform loads and the index chain is shorter.
__global__ void __launch_bounds__(256, 8)
eeg_augment_kernel(const float4* __restrict__ x,
                   const float4* __restrict__ chdrop_u,   // [B,32] float4 view of [B,1,N]
                   const float4* __restrict__ noise,
                   const float* __restrict__ tm_u,        // [B]
                   const int* __restrict__ t0,            // [B]
                   float4* __restrict__ out)
{
    const unsigned int blk = blockIdx.x;
    const unsigned int b   = blk >> 7;                 // 128 blocks per b (2048*32/512)
    const unsigned int base = blk * 512u + threadIdx.x;

    // Block-uniform per-sample mask parameters (uniform-register loads)
    const bool  apply = __ldg(tm_u + b) < P_TIMEMASK;
    const int   ts    = __ldg(t0 + b);

    const float4* __restrict__ cu_row = chdrop_u + (b << 5);

    #pragma unroll
    for (int k = 0; k < 2; k++) {
        unsigned int i  = base + (unsigned int)k * 256u;
        unsigned int n4 = i & 31u;                     // float4 index within N
        int          t  = (int)((i >> 5) & (T_DIM - 1));

        bool masked = apply & (t >= ts) & (t < ts + MLEN);

        float4 o;
        if (masked) {
            o.x = 0.0f; o.y = 0.0f; o.z = 0.0f; o.w = 0.0f;
        } else {
            float4 xv = __ldcs(x + i);
            float4 nv = __ldcs(noise + i);
            float4 cu = __ldg(cu_row + n4);            // tiny, L1-resident

            o.x = (cu.x < P_CHDROP ? 0.0f : xv.x) + NOISE_STD * nv.x;
            o.y = (cu.y < P_CHDROP ? 0.0f : xv.y) + NOISE_STD * nv.y;
            o.z = (cu.z < P_CHDROP ? 0.0f : xv.z) + NOISE_STD * nv.z;
            o.w = (cu.w < P_CHDROP ? 0.0f : xv.w) + NOISE_STD * nv.w;
        }
        __stcs(out + i, o);
    }
}

extern "C" void kernel_launch(void* const* d_in, const int* in_sizes, int n_in,
                              void* d_out, int out_size)
{
    // metadata order: x, chdrop_u, noise, tm_u, t0
    const float4* x      = (const float4*)d_in[0];
    const float4* cu     = (const float4*)d_in[1];
    const float4* noise  = (const float4*)d_in[2];
    const float*  tm_u   = (const float*)d_in[3];
    const int*    t0     = (const int*)d_in[4];
    float4*       out    = (float4*)d_out;

    // 256*2048*128 f32 = 16,777,216 float4; 512 per block -> 32768 blocks
    eeg_augment_kernel<<<32768u, 256u>>>(x, cu, noise, tm_u, t0, out);
}